// round 4
// baseline (speedup 1.0000x reference)
#include <cuda_runtime.h>
#include <cuda_bf16.h>
#include <cstdint>

#define BATCH   32
#define NNODES  128
#define NIN     128
#define NHID    256
#define NOUT    128
#define MROWS   (BATCH * NNODES)   // 4096

// Scratch (device globals: allocation-free rule)
__device__ float g_AC[MROWS * 512];   // 0..255 = A = X@W1_top ; 256..511 = C = X@W1_bot + b1
__device__ float g_S [MROWS * NHID];  // S[b,n,:] = sum_{i!=n} relu(A[b,i,:] + C[b,n,:])
__device__ float g_P [2][MROWS * NOUT]; // gemm2 k-split partials

typedef unsigned long long u64;

__device__ __forceinline__ u64 pk_dup(float x) {
    u64 r; asm("mov.b64 %0, {%1,%1};" : "=l"(r) : "f"(x)); return r;
}
__device__ __forceinline__ float2 upk(u64 v) {
    float2 r; asm("mov.b64 {%0,%1}, %2;" : "=f"(r.x), "=f"(r.y) : "l"(v)); return r;
}
__device__ __forceinline__ u64 fma2(u64 a, u64 b, u64 c) {
    u64 d; asm("fma.rn.f32x2 %0, %1, %2, %3;" : "=l"(d) : "l"(a), "l"(b), "l"(c)); return d;
}
__device__ __forceinline__ void relu_acc(u64& acc, u64 a, u64 c) {
    asm("{\n\t"
        ".reg .b64 s;\n\t"
        ".reg .f32 lo, hi;\n\t"
        "add.rn.f32x2 s, %1, %2;\n\t"
        "mov.b64 {lo, hi}, s;\n\t"
        "max.f32 lo, lo, 0f00000000;\n\t"
        "max.f32 hi, hi, 0f00000000;\n\t"
        "mov.b64 s, {lo, hi};\n\t"
        "add.rn.f32x2 %0, %0, s;\n\t"
        "}" : "+l"(acc) : "l"(a), "l"(c));
}
__device__ __forceinline__ void cpa16(uint32_t saddr, const void* g) {
    asm volatile("cp.async.ca.shared.global [%0], [%1], 16;" :: "r"(saddr), "l"(g));
}
#define CP_COMMIT() asm volatile("cp.async.commit_group;")
#define CP_WAIT0()  asm volatile("cp.async.wait_group 0;" ::: "memory")

// ---------------------------------------------------------------------------
// Kernel 1: AC[m,f] = X[m,:] @ W1eff (+b1 on C-half)
// M=4096, N=512, K=128. Block 64m x 128n, 128 thr, thread 8m x 8n (4 f32x2 pairs).
// k-chunks of 16, double-buffered. W via cp.async (no transpose), X via reg+STS.
// Grid (4, 64) = 256 CTAs.
// ---------------------------------------------------------------------------
__global__ __launch_bounds__(128) void gemm1_kernel(const float* __restrict__ X,
                                                    const float* __restrict__ W1,
                                                    const float* __restrict__ b1)
{
    const int bm = blockIdx.y * 64;
    const int bn = blockIdx.x * 128;          // 0,128,256,384
    const bool isC = (bn >= 256);
    const int  wcol  = isC ? (bn - 256) : bn;
    const int  wrow0 = isC ? 128 : 0;

    __shared__ __align__(16) float Xs[2][16][68];   // [k][m], 272B rows (16B-aligned, bank-shifted)
    __shared__ __align__(16) float Ws[2][16][132];  // [k][n], 528B rows

    const int tid = threadIdx.x;
    const int tx  = tid & 15;            // n-group: n = tx*8
    const int ty  = tid >> 4;            // m-group: m = ty*8 (0..7)

    // X loader: 64m x 16k per stage; thread: m = tid>>1, k-half = tid&1
    const int xm = tid >> 1;
    const int xk = (tid & 1) * 8;
    // W loader: 16k x 128n per stage via cp.async; thread: k = tid>>3, n0 = (tid&7)*16
    const int wk = tid >> 3;
    const int wn = (tid & 7) * 16;
    const float* wsrc = &W1[(wrow0 + wk) * NHID + wcol + wn];

    float4 xr0, xr1;
    u64 acc[8][4] = {};

#define G1_XLOAD(k0) do {                                                     \
    const float* xp = &X[(bm + xm) * NIN + (k0) + xk];                        \
    xr0 = *(const float4*)xp;  xr1 = *(const float4*)(xp + 4);                \
} while (0)
#define G1_XSTS(p) do {                                                       \
    Xs[p][xk+0][xm] = xr0.x; Xs[p][xk+1][xm] = xr0.y;                         \
    Xs[p][xk+2][xm] = xr0.z; Xs[p][xk+3][xm] = xr0.w;                         \
    Xs[p][xk+4][xm] = xr1.x; Xs[p][xk+5][xm] = xr1.y;                         \
    Xs[p][xk+6][xm] = xr1.z; Xs[p][xk+7][xm] = xr1.w;                         \
} while (0)
#define G1_WCP(p, k0) do {                                                    \
    uint32_t sa = (uint32_t)__cvta_generic_to_shared(&Ws[p][wk][wn]);         \
    const float* gp = wsrc + (size_t)(k0) * NHID;                             \
    cpa16(sa,      gp);                                                       \
    cpa16(sa + 16, gp + 4);                                                   \
    cpa16(sa + 32, gp + 8);                                                   \
    cpa16(sa + 48, gp + 12);                                                  \
} while (0)

    // prologue: stage 0
    G1_XLOAD(0);
    G1_WCP(0, 0);
    CP_COMMIT();
    G1_XSTS(0);
    CP_WAIT0();
    __syncthreads();

#pragma unroll
    for (int s = 0; s < 8; s++) {
        const int p = s & 1;
        if (s < 7) {
            G1_XLOAD((s + 1) * 16);
            G1_WCP(1 - p, (s + 1) * 16);
            CP_COMMIT();
        }
#pragma unroll
        for (int k = 0; k < 16; k++) {
            float4 xa = *(const float4*)&Xs[p][k][ty * 8];
            float4 xb = *(const float4*)&Xs[p][k][ty * 8 + 4];
            ulonglong2 wa = *(const ulonglong2*)&Ws[p][k][tx * 8];
            ulonglong2 wb = *(const ulonglong2*)&Ws[p][k][tx * 8 + 4];
            u64 xd[8];
            xd[0] = pk_dup(xa.x); xd[1] = pk_dup(xa.y);
            xd[2] = pk_dup(xa.z); xd[3] = pk_dup(xa.w);
            xd[4] = pk_dup(xb.x); xd[5] = pk_dup(xb.y);
            xd[6] = pk_dup(xb.z); xd[7] = pk_dup(xb.w);
#pragma unroll
            for (int i = 0; i < 8; i++) {
                acc[i][0] = fma2(xd[i], wa.x, acc[i][0]);
                acc[i][1] = fma2(xd[i], wa.y, acc[i][1]);
                acc[i][2] = fma2(xd[i], wb.x, acc[i][2]);
                acc[i][3] = fma2(xd[i], wb.y, acc[i][3]);
            }
        }
        if (s < 7) {
            G1_XSTS(1 - p);
            CP_WAIT0();
            __syncthreads();
        }
    }

    // epilogue: 8 rows x 8 consecutive n -> 2 STG.128 per row
    float4 bva = {0,0,0,0}, bvb = {0,0,0,0};
    if (isC) {
        bva = *(const float4*)&b1[bn - 256 + tx * 8];
        bvb = *(const float4*)&b1[bn - 256 + tx * 8 + 4];
    }
#pragma unroll
    for (int i = 0; i < 8; i++) {
        const int m = bm + ty * 8 + i;
        float2 p0 = upk(acc[i][0]), p1 = upk(acc[i][1]);
        float2 p2 = upk(acc[i][2]), p3 = upk(acc[i][3]);
        float4 v0 = {p0.x + bva.x, p0.y + bva.y, p1.x + bva.z, p1.y + bva.w};
        float4 v1 = {p2.x + bvb.x, p2.y + bvb.y, p3.x + bvb.z, p3.y + bvb.w};
        float* dst = &g_AC[m * 512 + bn + tx * 8];
        *(float4*)dst       = v0;
        *(float4*)(dst + 4) = v1;
    }
#undef G1_XLOAD
#undef G1_XSTS
#undef G1_WCP
}

// ---------------------------------------------------------------------------
// Kernel 2: S[b,n,f] = sum_{i != n} relu(A[b,i,f] + C[b,n,f])   (unchanged, passes)
// ---------------------------------------------------------------------------
__global__ __launch_bounds__(256) void reduce_kernel()
{
    const int b  = blockIdx.y;
    const int ft = blockIdx.x * 16;

    __shared__ __align__(16) float As[128][16];
    __shared__ __align__(16) float Cs[128][16];

    const int tid = threadIdx.x;
    const float* base = g_AC + (size_t)(b * NNODES) * 512;

#pragma unroll
    for (int q = 0; q < 2; q++) {
        int idx = tid + q * 256;
        int i   = idx >> 2;
        int fg  = idx & 3;
        *(float4*)&As[i][fg * 4] = *(const float4*)&base[i * 512 + ft + fg * 4];
        *(float4*)&Cs[i][fg * 4] = *(const float4*)&base[i * 512 + 256 + ft + fg * 4];
    }
    __syncthreads();

    const int f4 = (tid & 3) * 4;
    const int ng = tid >> 2;

    u64 c0[2], c1[2], acc0[2] = {}, acc1[2] = {};
#pragma unroll
    for (int r = 0; r < 2; r++) {
        const int n = ng + 64 * r;
        ulonglong2 cc = *(const ulonglong2*)&Cs[n][f4];
        c0[r] = cc.x; c1[r] = cc.y;
    }

#pragma unroll 8
    for (int i = 0; i < 128; i++) {
        ulonglong2 a = *(const ulonglong2*)&As[i][f4];
#pragma unroll
        for (int r = 0; r < 2; r++) {
            relu_acc(acc0[r], a.x, c0[r]);
            relu_acc(acc1[r], a.y, c1[r]);
        }
    }

#pragma unroll
    for (int r = 0; r < 2; r++) {
        const int n = ng + 64 * r;
        float4 a = *(const float4*)&As[n][f4];
        float2 cx = upk(c0[r]), cy = upk(c1[r]);
        float2 s0 = upk(acc0[r]), s1 = upk(acc1[r]);
        float4 out;
        out.x = s0.x - fmaxf(a.x + cx.x, 0.f);
        out.y = s0.y - fmaxf(a.y + cx.y, 0.f);
        out.z = s1.x - fmaxf(a.z + cy.x, 0.f);
        out.w = s1.y - fmaxf(a.w + cy.y, 0.f);
        *(float4*)&g_S[(size_t)(b * NNODES + n) * NHID + ft + f4] = out;
    }
}

// ---------------------------------------------------------------------------
// Kernel 3: partial GEMM  P[z][m,n] = S[m, z*128 : z*128+128] @ W2[z*128 : , n]
// Block 32m x 128n, 128 thr, thread 4m x 8n. k-chunks 16, double-buffered.
// Grid (1, 128, 2) = 256 CTAs.
// ---------------------------------------------------------------------------
__global__ __launch_bounds__(128) void gemm2_kernel(const float* __restrict__ W2)
{
    const int bm = blockIdx.y * 32;
    const int z  = blockIdx.z;
    const int kbase = z * 128;

    __shared__ __align__(16) float Ss[2][16][36];   // [k][m], 144B rows
    __shared__ __align__(16) float Ws[2][16][132];  // [k][n]

    const int tid = threadIdx.x;
    const int tx  = tid & 15;            // n = tx*8
    const int ty  = tid >> 4;            // m = ty*4

    // S loader: 32m x 16k; thread m = tid>>2, kq = (tid&3)*4
    const int sm = tid >> 2;
    const int sk = (tid & 3) * 4;
    // W loader: k = tid>>3, n0 = (tid&7)*16
    const int wk = tid >> 3;
    const int wn = (tid & 7) * 16;
    const float* wsrc = &W2[(kbase + wk) * NOUT + wn];

    float4 sr;
    u64 acc[4][4] = {};

#define G2_SLOAD(k0) do {                                                     \
    sr = *(const float4*)&g_S[(size_t)(bm + sm) * NHID + kbase + (k0) + sk];  \
} while (0)
#define G2_SSTS(p) do {                                                       \
    Ss[p][sk+0][sm] = sr.x; Ss[p][sk+1][sm] = sr.y;                           \
    Ss[p][sk+2][sm] = sr.z; Ss[p][sk+3][sm] = sr.w;                           \
} while (0)
#define G2_WCP(p, k0) do {                                                    \
    uint32_t sa = (uint32_t)__cvta_generic_to_shared(&Ws[p][wk][wn]);         \
    const float* gp = wsrc + (size_t)(k0) * NOUT;                             \
    cpa16(sa,      gp);                                                       \
    cpa16(sa + 16, gp + 4);                                                   \
    cpa16(sa + 32, gp + 8);                                                   \
    cpa16(sa + 48, gp + 12);                                                  \
} while (0)

    G2_SLOAD(0);
    G2_WCP(0, 0);
    CP_COMMIT();
    G2_SSTS(0);
    CP_WAIT0();
    __syncthreads();

#pragma unroll
    for (int s = 0; s < 8; s++) {
        const int p = s & 1;
        if (s < 7) {
            G2_SLOAD((s + 1) * 16);
            G2_WCP(1 - p, (s + 1) * 16);
            CP_COMMIT();
        }
#pragma unroll
        for (int k = 0; k < 16; k++) {
            float4 xa = *(const float4*)&Ss[p][k][ty * 4];
            ulonglong2 wa = *(const ulonglong2*)&Ws[p][k][tx * 8];
            ulonglong2 wb = *(const ulonglong2*)&Ws[p][k][tx * 8 + 4];
            u64 xd[4];
            xd[0] = pk_dup(xa.x); xd[1] = pk_dup(xa.y);
            xd[2] = pk_dup(xa.z); xd[3] = pk_dup(xa.w);
#pragma unroll
            for (int i = 0; i < 4; i++) {
                acc[i][0] = fma2(xd[i], wa.x, acc[i][0]);
                acc[i][1] = fma2(xd[i], wa.y, acc[i][1]);
                acc[i][2] = fma2(xd[i], wb.x, acc[i][2]);
                acc[i][3] = fma2(xd[i], wb.y, acc[i][3]);
            }
        }
        if (s < 7) {
            G2_SSTS(1 - p);
            CP_WAIT0();
            __syncthreads();
        }
    }

#pragma unroll
    for (int i = 0; i < 4; i++) {
        const int m = bm + ty * 4 + i;
        float2 p0 = upk(acc[i][0]), p1 = upk(acc[i][1]);
        float2 p2 = upk(acc[i][2]), p3 = upk(acc[i][3]);
        float4 v0 = {p0.x, p0.y, p1.x, p1.y};
        float4 v1 = {p2.x, p2.y, p3.x, p3.y};
        float* dst = &g_P[z][m * NOUT + tx * 8];
        *(float4*)dst       = v0;
        *(float4*)(dst + 4) = v1;
    }
#undef G2_SLOAD
#undef G2_SSTS
#undef G2_WCP
}

// ---------------------------------------------------------------------------
// Kernel 4: out = (P0 + P1 + 127*b2) / (127 + 1e-6)
// ---------------------------------------------------------------------------
__global__ __launch_bounds__(256) void combine_kernel(const float* __restrict__ b2,
                                                      float* __restrict__ out)
{
    const int idx = blockIdx.x * 256 + threadIdx.x;   // float4 index
    const int off = idx * 4;
    const int n0  = off & (NOUT - 1);
    float4 p0 = *(const float4*)&g_P[0][off];
    float4 p1 = *(const float4*)&g_P[1][off];
    float4 bb = *(const float4*)&b2[n0];
    const float inv = 1.0f / (127.0f + 1e-6f);
    float4 v;
    v.x = (p0.x + p1.x + 127.0f * bb.x) * inv;
    v.y = (p0.y + p1.y + 127.0f * bb.y) * inv;
    v.z = (p0.z + p1.z + 127.0f * bb.z) * inv;
    v.w = (p0.w + p1.w + 127.0f * bb.w) * inv;
    *(float4*)&out[off] = v;
}

// ---------------------------------------------------------------------------
// Launch. Inputs: x, rel_type, rel_rec, rel_send, W1, b1, W2, b2.
// rel_type unused; rel_rec/rel_send encode the fixed fully-connected
// off-diagonal graph (in-degree 127), exploited algebraically.
// ---------------------------------------------------------------------------
extern "C" void kernel_launch(void* const* d_in, const int* in_sizes, int n_in,
                              void* d_out, int out_size)
{
    const float* x  = (const float*)d_in[0];
    const float* W1 = (const float*)d_in[4];
    const float* b1 = (const float*)d_in[5];
    const float* W2 = (const float*)d_in[6];
    const float* b2 = (const float*)d_in[7];
    float* out = (float*)d_out;

    gemm1_kernel<<<dim3(4, 64), 128>>>(x, W1, b1);            // 256 CTAs
    reduce_kernel<<<dim3(NHID/16, BATCH), 256>>>();           // 512 CTAs
    gemm2_kernel<<<dim3(1, 128, 2), 128>>>(W2);               // 256 CTAs
    combine_kernel<<<MROWS * NOUT / 1024, 256>>>(b2, out);    // 512 CTAs
}